// round 5
// baseline (speedup 1.0000x reference)
#include <cuda_runtime.h>
#include <cuda_bf16.h>

#define NB   8
#define NC   512
#define NHW  1024
#define NH   8
#define HD   64
#define NG   32
#define CPG  16

// -------- scratch (static device arrays; no cudaMalloc allowed) --------
__device__ float g_xn [NB*NC*NHW];        // 16 MB  groupnorm output
__device__ float g_qkv[NB*3*NC*NHW];      // 48 MB  qkv activations
__device__ float g_att[NB*NC*NHW];        // 16 MB  attention output

typedef unsigned long long u64;

// -------- f32x2 packed-FMA helpers (sm_100+) --------
__device__ __forceinline__ void ffma2(u64 &acc, u64 a, u64 b){
    asm("fma.rn.f32x2 %0, %1, %2, %0;" : "+l"(acc) : "l"(a), "l"(b));
}
__device__ __forceinline__ u64 bcast2(float a){
    u64 r; asm("mov.b64 %0, {%1, %1};" : "=l"(r) : "f"(a)); return r;
}
__device__ __forceinline__ float2 unpk(u64 v){
    float2 r; asm("mov.b64 {%0, %1}, %2;" : "=f"(r.x), "=f"(r.y) : "l"(v)); return r;
}

// ============================================================================
// GroupNorm: one block per (batch, group); group span is contiguous 16*1024 f32
// ============================================================================
__global__ void __launch_bounds__(256)
gn_kernel(const float* __restrict__ x,
          const float* __restrict__ gw,
          const float* __restrict__ gb)
{
    const int GSZ4 = CPG*NHW/4;                 // 4096 float4 per group
    int bg = blockIdx.x;
    int g  = bg & (NG-1);
    const float4* xp = (const float4*)(x + (size_t)bg*CPG*NHW);
    float4*       op = (float4*)(g_xn + (size_t)bg*CPG*NHW);

    float s = 0.f, s2 = 0.f;
    for (int i = threadIdx.x; i < GSZ4; i += 256){
        float4 v = xp[i];
        s  += (v.x+v.y)+(v.z+v.w);
        s2 += (v.x*v.x+v.y*v.y)+(v.z*v.z+v.w*v.w);
    }
    #pragma unroll
    for (int m=16;m;m>>=1){
        s  += __shfl_xor_sync(0xffffffffu, s,  m);
        s2 += __shfl_xor_sync(0xffffffffu, s2, m);
    }
    __shared__ float shA[8], shB[8], shMu, shRs;
    int w = threadIdx.x>>5, l = threadIdx.x&31;
    if (l==0){ shA[w]=s; shB[w]=s2; }
    __syncthreads();
    if (threadIdx.x==0){
        float S=0.f, S2=0.f;
        #pragma unroll
        for (int i=0;i<8;i++){ S+=shA[i]; S2+=shB[i]; }
        const float inv = 1.f/(float)(CPG*NHW);
        float mu  = S*inv;
        float var = S2*inv - mu*mu;
        shMu = mu; shRs = rsqrtf(var + 1e-5f);
    }
    __syncthreads();
    float mu = shMu, rstd = shRs;
    for (int i = threadIdx.x; i < GSZ4; i += 256){
        float4 v = xp[i];
        int cl = i >> 8;                        // 256 float4 per channel
        float a = gw[g*CPG+cl]*rstd;
        float c = gb[g*CPG+cl] - mu*a;
        float4 o;
        o.x=v.x*a+c; o.y=v.y*a+c; o.z=v.z*a+c; o.w=v.w*a+c;
        op[i]=o;
    }
}

// ============================================================================
// SGEMM: C[z][m][n] = A[m][k]*B[z][k][n] + bias[m] (+ res)   N == 1024
// 128x128x8 tile, 256 threads, 8x8 micro-tile, f32x2-packed accumulators
// ============================================================================
__global__ void __launch_bounds__(256)
sgemm_kernel(const float* __restrict__ A,
             const float* __restrict__ Bm,
             const float* __restrict__ bias,
             const float* __restrict__ res,
             float* __restrict__ Cm,
             int M, int K)
{
    __shared__ float As[8][128];   // [k][m]
    __shared__ float Bs[8][128];   // [k][n]
    const int tid = threadIdx.x;
    const int tx = tid & 15, ty = tid >> 4;
    const int m0 = blockIdx.y*128, n0 = blockIdx.x*128;
    const size_t zB = (size_t)blockIdx.z * (size_t)K * 1024u;
    const size_t zC = (size_t)blockIdx.z * (size_t)M * 1024u;

    const int ar = tid>>1,  ac = (tid&1)*4;
    const int br = tid>>5,  bc = (tid&31)*4;
    const float* Ag = A  +       (size_t)(m0+ar)*K + ac;
    const float* Bg = Bm + zB +  (size_t)br*1024 + n0 + bc;

    {   // first k-tile
        float4 av = *(const float4*)Ag;
        float4 bv = *(const float4*)Bg;
        As[ac+0][ar]=av.x; As[ac+1][ar]=av.y; As[ac+2][ar]=av.z; As[ac+3][ar]=av.w;
        *(float4*)&Bs[br][bc] = bv;
    }
    __syncthreads();

    u64 acc[8][4];
    #pragma unroll
    for (int i=0;i<8;i++)
        #pragma unroll
        for (int j=0;j<4;j++) acc[i][j]=0ull;   // packed {0.f,0.f}

    const int rm = ty*8, cn = tx*8;

    for (int kt=0; kt<K; kt+=8){
        float4 an, bn;
        const bool more = (kt+8) < K;
        if (more){
            an = *(const float4*)(Ag + kt + 8);
            bn = *(const float4*)(Bg + (size_t)(kt+8)*1024);
        }
        #pragma unroll
        for (int kk=0;kk<8;kk++){
            float4 t0 = *(const float4*)&As[kk][rm];
            float4 t1 = *(const float4*)&As[kk][rm+4];
            const u64* bp = (const u64*)&Bs[kk][cn];
            u64 b0=bp[0], b1=bp[1], b2=bp[2], b3=bp[3];
            float a[8]={t0.x,t0.y,t0.z,t0.w,t1.x,t1.y,t1.z,t1.w};
            #pragma unroll
            for (int i=0;i<8;i++){
                u64 a2 = bcast2(a[i]);
                ffma2(acc[i][0],a2,b0);
                ffma2(acc[i][1],a2,b1);
                ffma2(acc[i][2],a2,b2);
                ffma2(acc[i][3],a2,b3);
            }
        }
        if (more){
            __syncthreads();
            As[ac+0][ar]=an.x; As[ac+1][ar]=an.y; As[ac+2][ar]=an.z; As[ac+3][ar]=an.w;
            *(float4*)&Bs[br][bc]=bn;
            __syncthreads();
        }
    }

    #pragma unroll
    for (int i=0;i<8;i++){
        const int m = m0 + rm + i;
        const float bi = bias[m];
        float o[8];
        #pragma unroll
        for (int j=0;j<4;j++){
            float2 p = unpk(acc[i][j]);
            o[2*j]=p.x+bi; o[2*j+1]=p.y+bi;
        }
        float* cp = Cm + zC + (size_t)m*1024 + n0 + cn;
        if (res){
            const float* rp = res + zC + (size_t)m*1024 + n0 + cn;
            float4 r0=*(const float4*)rp, r1=*(const float4*)(rp+4);
            o[0]+=r0.x;o[1]+=r0.y;o[2]+=r0.z;o[3]+=r0.w;
            o[4]+=r1.x;o[5]+=r1.y;o[6]+=r1.z;o[7]+=r1.w;
        }
        *(float4*)cp     = make_float4(o[0],o[1],o[2],o[3]);
        *(float4*)(cp+4) = make_float4(o[4],o[5],o[6],o[7]);
    }
}

// ============================================================================
// Fused flash attention (fp32). One block per (b, h, 64-query tile).
// 256 threads = 16x16; per-thread 4x4 micro-tiles; 64-wide KV tiles,
// online softmax. smem layouts put the reduction dim on the row index:
//   Qs,Ks: [d][q/m]   Vs: [m][d]   Ps: [q][m]   (stride 68)
// ============================================================================
__global__ void __launch_bounds__(256,2)
attn_kernel()
{
    extern __shared__ float sm[];
    float* Qs = sm;                 // 64 x 68 (reused as O[d][q] at the end)
    float* Ks = sm + 64*68;
    float* Vs = sm + 2*64*68;
    float* Ps = sm + 3*64*68;

    const int tid = threadIdx.x;
    const int tx = tid & 15, ty = tid >> 4;
    const int qb = ty*4, db = tx*4;
    const int q0 = blockIdx.x*64;
    const int h  = blockIdx.y, b = blockIdx.z;

    const float* qp = g_qkv + ((size_t)b*3*NC + (size_t)h*HD)*NHW;
    const float* kp = qp + (size_t)NC*NHW;
    const float* vp = qp + (size_t)(2*NC)*NHW;
    float*       op = g_att + ((size_t)b*NC + (size_t)h*HD)*NHW;

    #pragma unroll
    for (int it=0; it<4; it++){
        int i = tid + it*256;
        int d = i>>4, f=(i&15)*4;
        *(float4*)&Qs[d*68+f] = *(const float4*)&qp[(size_t)d*NHW + q0 + f];
    }

    float m_run[4], l_run[4], acc[4][4];
    #pragma unroll
    for (int i=0;i<4;i++){
        m_run[i]=-1e30f; l_run[i]=0.f;
        #pragma unroll
        for (int j=0;j<4;j++) acc[i][j]=0.f;
    }
    __syncthreads();

    for (int t=0;t<16;t++){
        const int m0 = t*64;
        #pragma unroll
        for (int it=0; it<4; it++){
            int i = tid + it*256;
            int d = i>>4, f=(i&15)*4;
            *(float4*)&Ks[d*68+f] = *(const float4*)&kp[(size_t)d*NHW + m0 + f];
            float4 vv = *(const float4*)&vp[(size_t)d*NHW + m0 + f];
            Vs[(f+0)*68+d]=vv.x; Vs[(f+1)*68+d]=vv.y;
            Vs[(f+2)*68+d]=vv.z; Vs[(f+3)*68+d]=vv.w;     // -> [m][d]
        }
        __syncthreads();

        // ---- S = (Q^T K)/8, thread tile 4q x 4m ----
        float s[4][4];
        #pragma unroll
        for (int i=0;i<4;i++)
            #pragma unroll
            for (int j=0;j<4;j++) s[i][j]=0.f;

        #pragma unroll 8
        for (int d=0; d<64; d++){
            float4 qv = *(const float4*)&Qs[d*68+qb];
            float4 kv = *(const float4*)&Ks[d*68+db];
            float qa[4]={qv.x,qv.y,qv.z,qv.w};
            float ka[4]={kv.x,kv.y,kv.z,kv.w};
            #pragma unroll
            for (int i=0;i<4;i++)
                #pragma unroll
                for (int j=0;j<4;j++) s[i][j] += qa[i]*ka[j];
        }

        // ---- online softmax per q-row (row spread over 16 tx lanes) ----
        #pragma unroll
        for (int i=0;i<4;i++){
            #pragma unroll
            for (int j=0;j<4;j++) s[i][j] *= 0.125f;      // 1/sqrt(64)
            float rmax = fmaxf(fmaxf(s[i][0],s[i][1]),fmaxf(s[i][2],s[i][3]));
            #pragma unroll
            for (int mk=1; mk<16; mk<<=1)
                rmax = fmaxf(rmax, __shfl_xor_sync(0xffffffffu, rmax, mk));
            float mn   = fmaxf(m_run[i], rmax);
            float corr = __expf(m_run[i]-mn);
            m_run[i]   = mn;
            float rs=0.f;
            #pragma unroll
            for (int j=0;j<4;j++){ float p=__expf(s[i][j]-mn); s[i][j]=p; rs+=p; }
            #pragma unroll
            for (int mk=1; mk<16; mk<<=1)
                rs += __shfl_xor_sync(0xffffffffu, rs, mk);
            l_run[i] = l_run[i]*corr + rs;
            #pragma unroll
            for (int j=0;j<4;j++) acc[i][j]*=corr;
            *(float4*)&Ps[(qb+i)*68+db] = make_float4(s[i][0],s[i][1],s[i][2],s[i][3]);
        }
        __syncthreads();

        // ---- acc += P @ V, thread tile 4q x 4d ----
        #pragma unroll 4
        for (int m=0; m<64; m++){
            float4 pv = *(const float4*)&Vs[m*68+db];
            float p0 = Ps[(qb+0)*68+m];
            float p1 = Ps[(qb+1)*68+m];
            float p2 = Ps[(qb+2)*68+m];
            float p3 = Ps[(qb+3)*68+m];
            acc[0][0]+=p0*pv.x; acc[0][1]+=p0*pv.y; acc[0][2]+=p0*pv.z; acc[0][3]+=p0*pv.w;
            acc[1][0]+=p1*pv.x; acc[1][1]+=p1*pv.y; acc[1][2]+=p1*pv.z; acc[1][3]+=p1*pv.w;
            acc[2][0]+=p2*pv.x; acc[2][1]+=p2*pv.y; acc[2][2]+=p2*pv.z; acc[2][3]+=p2*pv.w;
            acc[3][0]+=p3*pv.x; acc[3][1]+=p3*pv.y; acc[3][2]+=p3*pv.z; acc[3][3]+=p3*pv.w;
        }
        __syncthreads();
    }

    // ---- normalize and write O (transpose via smem: Qs reused as O[d][q]) ----
    #pragma unroll
    for (int i=0;i<4;i++){
        float inv = 1.f/l_run[i];
        #pragma unroll
        for (int j=0;j<4;j++)
            Qs[(db+j)*68 + qb + i] = acc[i][j]*inv;
    }
    __syncthreads();
    #pragma unroll
    for (int it=0; it<4; it++){
        int i = tid + it*256;
        int d = i>>4, f=(i&15)*4;
        *(float4*)&op[(size_t)d*NHW + q0 + f] = *(const float4*)&Qs[d*68+f];
    }
}

// ============================================================================
extern "C" void kernel_launch(void* const* d_in, const int* in_sizes, int n_in,
                              void* d_out, int out_size)
{
    const float* x      = (const float*)d_in[0];
    const float* gn_w   = (const float*)d_in[1];
    const float* gn_b   = (const float*)d_in[2];
    const float* qkv_w  = (const float*)d_in[3];
    const float* qkv_b  = (const float*)d_in[4];
    const float* proj_w = (const float*)d_in[5];
    const float* proj_b = (const float*)d_in[6];
    float* out = (float*)d_out;

    float* xn;  cudaGetSymbolAddress((void**)&xn,  g_xn);
    float* qkv; cudaGetSymbolAddress((void**)&qkv, g_qkv);
    float* att; cudaGetSymbolAddress((void**)&att, g_att);

    static int smem_set = 0;
    const int ATT_SMEM = 4*64*68*sizeof(float);   // 69632 B
    if (!smem_set){
        cudaFuncSetAttribute(attn_kernel,
            cudaFuncAttributeMaxDynamicSharedMemorySize, ATT_SMEM);
        smem_set = 1;
    }

    // 1. GroupNorm
    gn_kernel<<<NB*NG, 256>>>(x, gn_w, gn_b);

    // 2. QKV projection: per batch [1536,512] x [512,1024]
    sgemm_kernel<<<dim3(8, 12, NB), 256>>>(qkv_w, xn, qkv_b, nullptr, qkv,
                                           3*NC, NC);

    // 3. Fused attention
    attn_kernel<<<dim3(NHW/64, NH, NB), 256, ATT_SMEM>>>();

    // 4. Output projection + residual
    sgemm_kernel<<<dim3(8, 4, NB), 256>>>(proj_w, att, proj_b, x, out,
                                          NC, NC);
}

// round 6
// speedup vs baseline: 1.1034x; 1.1034x over previous
#include <cuda_runtime.h>
#include <cuda_bf16.h>

#define NB   8
#define NC   512
#define NHW  1024
#define NH   8
#define HD   64
#define NG   32
#define CPG  16

// -------- scratch (static device arrays; no cudaMalloc allowed) --------
__device__ float g_xn [NB*NC*NHW];        // 16 MB  groupnorm output
__device__ float g_qkv[NB*3*NC*NHW];      // 48 MB  qkv activations
__device__ float g_att[NB*NC*NHW];        // 16 MB  attention output

typedef unsigned long long u64;

// -------- f32x2 packed helpers (sm_100+) --------
__device__ __forceinline__ void ffma2(u64 &acc, u64 a, u64 b){
    asm("fma.rn.f32x2 %0, %1, %2, %0;" : "+l"(acc) : "l"(a), "l"(b));
}
__device__ __forceinline__ void fmul2(u64 &a, u64 b){
    asm("mul.rn.f32x2 %0, %0, %1;" : "+l"(a) : "l"(b));
}
__device__ __forceinline__ u64 bcast2(float a){
    u64 r; asm("mov.b64 %0, {%1, %1};" : "=l"(r) : "f"(a)); return r;
}
__device__ __forceinline__ float2 unpk(u64 v){
    float2 r; asm("mov.b64 {%0, %1}, %2;" : "=f"(r.x), "=f"(r.y) : "l"(v)); return r;
}

// ============================================================================
// GroupNorm: one block per (batch, group); group span is contiguous 16*1024 f32
// ============================================================================
__global__ void __launch_bounds__(256)
gn_kernel(const float* __restrict__ x,
          const float* __restrict__ gw,
          const float* __restrict__ gb)
{
    const int GSZ4 = CPG*NHW/4;                 // 4096 float4 per group
    int bg = blockIdx.x;
    int g  = bg & (NG-1);
    const float4* xp = (const float4*)(x + (size_t)bg*CPG*NHW);
    float4*       op = (float4*)(g_xn + (size_t)bg*CPG*NHW);

    float s = 0.f, s2 = 0.f;
    for (int i = threadIdx.x; i < GSZ4; i += 256){
        float4 v = xp[i];
        s  += (v.x+v.y)+(v.z+v.w);
        s2 += (v.x*v.x+v.y*v.y)+(v.z*v.z+v.w*v.w);
    }
    #pragma unroll
    for (int m=16;m;m>>=1){
        s  += __shfl_xor_sync(0xffffffffu, s,  m);
        s2 += __shfl_xor_sync(0xffffffffu, s2, m);
    }
    __shared__ float shA[8], shB[8], shMu, shRs;
    int w = threadIdx.x>>5, l = threadIdx.x&31;
    if (l==0){ shA[w]=s; shB[w]=s2; }
    __syncthreads();
    if (threadIdx.x==0){
        float S=0.f, S2=0.f;
        #pragma unroll
        for (int i=0;i<8;i++){ S+=shA[i]; S2+=shB[i]; }
        const float inv = 1.f/(float)(CPG*NHW);
        float mu  = S*inv;
        float var = S2*inv - mu*mu;
        shMu = mu; shRs = rsqrtf(var + 1e-5f);
    }
    __syncthreads();
    float mu = shMu, rstd = shRs;
    for (int i = threadIdx.x; i < GSZ4; i += 256){
        float4 v = xp[i];
        int cl = i >> 8;                        // 256 float4 per channel
        float a = gw[g*CPG+cl]*rstd;
        float c = gb[g*CPG+cl] - mu*a;
        float4 o;
        o.x=v.x*a+c; o.y=v.y*a+c; o.z=v.z*a+c; o.w=v.w*a+c;
        op[i]=o;
    }
}

// ============================================================================
// SGEMM: C[z][m][n] = A[m][k]*B[z][k][n] + bias[m] (+ res)   N == 1024
// 128x128x8 tile, 256 threads, 8x8 micro-tile, f32x2-packed accumulators,
// double-buffered smem (one __syncthreads per k-step), 2 CTAs/SM.
// ============================================================================
__global__ void __launch_bounds__(256,2)
sgemm_kernel(const float* __restrict__ A,
             const float* __restrict__ Bm,
             const float* __restrict__ bias,
             const float* __restrict__ res,
             float* __restrict__ Cm,
             int M, int K)
{
    __shared__ float As[2][8][128];   // [buf][k][m]
    __shared__ float Bs[2][8][128];   // [buf][k][n]
    const int tid = threadIdx.x;
    const int tx = tid & 15, ty = tid >> 4;
    const int m0 = blockIdx.y*128, n0 = blockIdx.x*128;
    const size_t zB = (size_t)blockIdx.z * (size_t)K * 1024u;
    const size_t zC = (size_t)blockIdx.z * (size_t)M * 1024u;

    const int ar = tid>>1,  ac = (tid&1)*4;
    const int br = tid>>5,  bc = (tid&31)*4;
    const float* Ag = A  +       (size_t)(m0+ar)*K + ac;
    const float* Bg = Bm + zB +  (size_t)br*1024 + n0 + bc;

    {   // first k-tile -> buffer 0
        float4 av = *(const float4*)Ag;
        float4 bv = *(const float4*)Bg;
        As[0][ac+0][ar]=av.x; As[0][ac+1][ar]=av.y;
        As[0][ac+2][ar]=av.z; As[0][ac+3][ar]=av.w;
        *(float4*)&Bs[0][br][bc] = bv;
    }
    __syncthreads();

    u64 acc[8][4];
    #pragma unroll
    for (int i=0;i<8;i++)
        #pragma unroll
        for (int j=0;j<4;j++) acc[i][j]=0ull;   // packed {0.f,0.f}

    const int rm = ty*8, cn = tx*8;
    int p = 0;

    for (int kt=0; kt<K; kt+=8){
        float4 an, bn;
        const bool more = (kt+8) < K;
        if (more){
            an = *(const float4*)(Ag + kt + 8);
            bn = *(const float4*)(Bg + (size_t)(kt+8)*1024);
        }
        #pragma unroll
        for (int kk=0;kk<8;kk++){
            float4 t0 = *(const float4*)&As[p][kk][rm];
            float4 t1 = *(const float4*)&As[p][kk][rm+4];
            const u64* bp = (const u64*)&Bs[p][kk][cn];
            u64 b0=bp[0], b1=bp[1], b2=bp[2], b3=bp[3];
            float a[8]={t0.x,t0.y,t0.z,t0.w,t1.x,t1.y,t1.z,t1.w};
            #pragma unroll
            for (int i=0;i<8;i++){
                u64 a2 = bcast2(a[i]);
                ffma2(acc[i][0],a2,b0);
                ffma2(acc[i][1],a2,b1);
                ffma2(acc[i][2],a2,b2);
                ffma2(acc[i][3],a2,b3);
            }
        }
        if (more){
            int q = p^1;
            As[q][ac+0][ar]=an.x; As[q][ac+1][ar]=an.y;
            As[q][ac+2][ar]=an.z; As[q][ac+3][ar]=an.w;
            *(float4*)&Bs[q][br][bc]=bn;
            __syncthreads();
            p = q;
        }
    }

    #pragma unroll
    for (int i=0;i<8;i++){
        const int m = m0 + rm + i;
        const float bi = bias[m];
        float o[8];
        #pragma unroll
        for (int j=0;j<4;j++){
            float2 pr = unpk(acc[i][j]);
            o[2*j]=pr.x+bi; o[2*j+1]=pr.y+bi;
        }
        float* cp = Cm + zC + (size_t)m*1024 + n0 + cn;
        if (res){
            const float* rp = res + zC + (size_t)m*1024 + n0 + cn;
            float4 r0=*(const float4*)rp, r1=*(const float4*)(rp+4);
            o[0]+=r0.x;o[1]+=r0.y;o[2]+=r0.z;o[3]+=r0.w;
            o[4]+=r1.x;o[5]+=r1.y;o[6]+=r1.z;o[7]+=r1.w;
        }
        *(float4*)cp     = make_float4(o[0],o[1],o[2],o[3]);
        *(float4*)(cp+4) = make_float4(o[4],o[5],o[6],o[7]);
    }
}

// ============================================================================
// Fused flash attention (fp32, f32x2-packed). One block per (b,h,64-q tile).
// 256 threads = 16x16; per-thread 4x4 micro-tiles; 64-wide KV tiles with
// online softmax. smem layouts put the reduction dim on the row index:
//   Qs,Ks: [d][q/m]   Vs: [m][d]   Ps: [q][m]   (stride 68)
// S-phase accumulators packed along m; PV accumulators packed along d.
// ============================================================================
__global__ void __launch_bounds__(256,2)
attn_kernel()
{
    extern __shared__ float sm[];
    float* Qs = sm;                 // 64 x 68 (reused as O[d][q] at the end)
    float* Ks = sm + 64*68;
    float* Vs = sm + 2*64*68;
    float* Ps = sm + 3*64*68;

    const int tid = threadIdx.x;
    const int tx = tid & 15, ty = tid >> 4;
    const int qb = ty*4, db = tx*4;
    const int q0 = blockIdx.x*64;
    const int h  = blockIdx.y, b = blockIdx.z;

    const float* qp = g_qkv + ((size_t)b*3*NC + (size_t)h*HD)*NHW;
    const float* kp = qp + (size_t)NC*NHW;
    const float* vp = qp + (size_t)(2*NC)*NHW;
    float*       op = g_att + ((size_t)b*NC + (size_t)h*HD)*NHW;

    #pragma unroll
    for (int it=0; it<4; it++){
        int i = tid + it*256;
        int d = i>>4, f=(i&15)*4;
        *(float4*)&Qs[d*68+f] = *(const float4*)&qp[(size_t)d*NHW + q0 + f];
    }

    float m_run[4], l_run[4];
    u64 acc2[4][2];                 // [q][d-pair]
    #pragma unroll
    for (int i=0;i<4;i++){
        m_run[i]=-1e30f; l_run[i]=0.f;
        acc2[i][0]=0ull; acc2[i][1]=0ull;
    }
    __syncthreads();

    for (int t=0;t<16;t++){
        const int m0 = t*64;
        #pragma unroll
        for (int it=0; it<4; it++){
            int i = tid + it*256;
            int d = i>>4, f=(i&15)*4;
            *(float4*)&Ks[d*68+f] = *(const float4*)&kp[(size_t)d*NHW + m0 + f];
            float4 vv = *(const float4*)&vp[(size_t)d*NHW + m0 + f];
            Vs[(f+0)*68+d]=vv.x; Vs[(f+1)*68+d]=vv.y;
            Vs[(f+2)*68+d]=vv.z; Vs[(f+3)*68+d]=vv.w;     // -> [m][d]
        }
        __syncthreads();

        // ---- S = (Q^T K)/8, thread tile 4q x 4m, packed along m ----
        u64 s2[4][2];
        #pragma unroll
        for (int i=0;i<4;i++){ s2[i][0]=0ull; s2[i][1]=0ull; }

        #pragma unroll 8
        for (int d=0; d<64; d++){
            float4 qv = *(const float4*)&Qs[d*68+qb];
            const u64* kp2 = (const u64*)&Ks[d*68+db];
            u64 k0=kp2[0], k1=kp2[1];
            u64 a0=bcast2(qv.x), a1=bcast2(qv.y), a2=bcast2(qv.z), a3=bcast2(qv.w);
            ffma2(s2[0][0],a0,k0); ffma2(s2[0][1],a0,k1);
            ffma2(s2[1][0],a1,k0); ffma2(s2[1][1],a1,k1);
            ffma2(s2[2][0],a2,k0); ffma2(s2[2][1],a2,k1);
            ffma2(s2[3][0],a3,k0); ffma2(s2[3][1],a3,k1);
        }

        // ---- online softmax per q-row (row spread over 16 tx lanes) ----
        #pragma unroll
        for (int i=0;i<4;i++){
            float2 pa = unpk(s2[i][0]), pb = unpk(s2[i][1]);
            float s0=pa.x*0.125f, s1=pa.y*0.125f, s2v=pb.x*0.125f, s3=pb.y*0.125f;
            float rmax = fmaxf(fmaxf(s0,s1),fmaxf(s2v,s3));
            #pragma unroll
            for (int mk=1; mk<16; mk<<=1)
                rmax = fmaxf(rmax, __shfl_xor_sync(0xffffffffu, rmax, mk));
            float mn   = fmaxf(m_run[i], rmax);
            float corr = __expf(m_run[i]-mn);
            m_run[i]   = mn;
            float p0=__expf(s0-mn), p1=__expf(s1-mn);
            float p2=__expf(s2v-mn), p3=__expf(s3-mn);
            float rs = (p0+p1)+(p2+p3);
            #pragma unroll
            for (int mk=1; mk<16; mk<<=1)
                rs += __shfl_xor_sync(0xffffffffu, rs, mk);
            l_run[i] = l_run[i]*corr + rs;
            u64 c2 = bcast2(corr);
            fmul2(acc2[i][0], c2);
            fmul2(acc2[i][1], c2);
            *(float4*)&Ps[(qb+i)*68+db] = make_float4(p0,p1,p2,p3);
        }
        __syncthreads();

        // ---- acc += P @ V, thread tile 4q x 4d, packed along d ----
        #pragma unroll 4
        for (int m=0; m<64; m++){
            const u64* vp2 = (const u64*)&Vs[m*68+db];
            u64 v0=vp2[0], v1=vp2[1];
            u64 b0=bcast2(Ps[(qb+0)*68+m]);
            u64 b1=bcast2(Ps[(qb+1)*68+m]);
            u64 b2=bcast2(Ps[(qb+2)*68+m]);
            u64 b3=bcast2(Ps[(qb+3)*68+m]);
            ffma2(acc2[0][0],b0,v0); ffma2(acc2[0][1],b0,v1);
            ffma2(acc2[1][0],b1,v0); ffma2(acc2[1][1],b1,v1);
            ffma2(acc2[2][0],b2,v0); ffma2(acc2[2][1],b2,v1);
            ffma2(acc2[3][0],b3,v0); ffma2(acc2[3][1],b3,v1);
        }
        __syncthreads();
    }

    // ---- normalize and write O (transpose via smem: Qs reused as O[d][q]) ----
    #pragma unroll
    for (int i=0;i<4;i++){
        float inv = 1.f/l_run[i];
        float2 pa = unpk(acc2[i][0]), pb = unpk(acc2[i][1]);
        Qs[(db+0)*68 + qb + i] = pa.x*inv;
        Qs[(db+1)*68 + qb + i] = pa.y*inv;
        Qs[(db+2)*68 + qb + i] = pb.x*inv;
        Qs[(db+3)*68 + qb + i] = pb.y*inv;
    }
    __syncthreads();
    #pragma unroll
    for (int it=0; it<4; it++){
        int i = tid + it*256;
        int d = i>>4, f=(i&15)*4;
        *(float4*)&op[(size_t)d*NHW + q0 + f] = *(const float4*)&Qs[d*68+f];
    }
}

// ============================================================================
extern "C" void kernel_launch(void* const* d_in, const int* in_sizes, int n_in,
                              void* d_out, int out_size)
{
    const float* x      = (const float*)d_in[0];
    const float* gn_w   = (const float*)d_in[1];
    const float* gn_b   = (const float*)d_in[2];
    const float* qkv_w  = (const float*)d_in[3];
    const float* qkv_b  = (const float*)d_in[4];
    const float* proj_w = (const float*)d_in[5];
    const float* proj_b = (const float*)d_in[6];
    float* out = (float*)d_out;

    float* xn;  cudaGetSymbolAddress((void**)&xn,  g_xn);
    float* qkv; cudaGetSymbolAddress((void**)&qkv, g_qkv);
    float* att; cudaGetSymbolAddress((void**)&att, g_att);

    static int smem_set = 0;
    const int ATT_SMEM = 4*64*68*sizeof(float);   // 69632 B
    if (!smem_set){
        cudaFuncSetAttribute(attn_kernel,
            cudaFuncAttributeMaxDynamicSharedMemorySize, ATT_SMEM);
        smem_set = 1;
    }

    // 1. GroupNorm
    gn_kernel<<<NB*NG, 256>>>(x, gn_w, gn_b);

    // 2. QKV projection: per batch [1536,512] x [512,1024]
    sgemm_kernel<<<dim3(8, 12, NB), 256>>>(qkv_w, xn, qkv_b, nullptr, qkv,
                                           3*NC, NC);

    // 3. Fused attention
    attn_kernel<<<dim3(NHW/64, NH, NB), 256, ATT_SMEM>>>();

    // 4. Output projection + residual
    sgemm_kernel<<<dim3(8, 4, NB), 256>>>(proj_w, att, proj_b, x, out,
                                          NC, NC);
}

// round 8
// speedup vs baseline: 1.5178x; 1.3756x over previous
#include <cuda_runtime.h>
#include <cuda_bf16.h>
#include <cstdint>

#define NB   8
#define NC   512
#define NHW  1024
#define NH   8
#define HD   64
#define NG   32
#define CPG  16

// -------- scratch (static device arrays; no cudaMalloc allowed) --------
__device__ float g_xn [NB*NC*NHW];              // 16 MB  groupnorm output (fp32)
__device__ float g_qkv[NB*3*NC*NHW];            // 48 MB  qkv activations (fp32)
__device__ float g_att[NB*NC*NHW];              // 16 MB  attention output (fp32)
__device__ __nv_bfloat16 g_wA[3*NC*2*NC];       //  3 MB  qkv_w  hi|lo  [1536][1024]
__device__ __nv_bfloat16 g_wP[NC*2*NC];         //  1 MB  proj_w hi|lo  [512][1024]
__device__ __nv_bfloat16 g_xT[NB*NHW*2*NC];     // 16 MB  xn^T   hi|lo  [z][1024][1024]
__device__ __nv_bfloat16 g_aT[NB*NHW*2*NC];     // 16 MB  att^T  hi|lo  [z][1024][1024]

typedef unsigned long long u64;

// -------- f32x2 packed helpers (sm_100+) --------
__device__ __forceinline__ void ffma2(u64 &acc, u64 a, u64 b){
    asm("fma.rn.f32x2 %0, %1, %2, %0;" : "+l"(acc) : "l"(a), "l"(b));
}
__device__ __forceinline__ void fmul2(u64 &a, u64 b){
    asm("mul.rn.f32x2 %0, %0, %1;" : "+l"(a) : "l"(b));
}
__device__ __forceinline__ u64 bcast2(float a){
    u64 r; asm("mov.b64 %0, {%1, %1};" : "=l"(r) : "f"(a)); return r;
}
__device__ __forceinline__ float2 unpk(u64 v){
    float2 r; asm("mov.b64 {%0, %1}, %2;" : "=f"(r.x), "=f"(r.y) : "l"(v)); return r;
}

// -------- mma.sync helpers (arch-generic, no 'a' feature needed) --------
__device__ __forceinline__ uint32_t smem_u32(const void* p){
    uint32_t a;
    asm("{ .reg .u64 t; cvta.to.shared.u64 t, %1; cvt.u32.u64 %0, t; }"
        : "=r"(a) : "l"(p));
    return a;
}
__device__ __forceinline__ void ldmx4(uint32_t* r, uint32_t addr){
    asm volatile("ldmatrix.sync.aligned.m8n8.x4.shared.b16 {%0,%1,%2,%3}, [%4];"
        : "=r"(r[0]),"=r"(r[1]),"=r"(r[2]),"=r"(r[3]) : "r"(addr));
}
__device__ __forceinline__ void ldmx2(uint32_t* r, uint32_t addr){
    asm volatile("ldmatrix.sync.aligned.m8n8.x2.shared.b16 {%0,%1}, [%2];"
        : "=r"(r[0]),"=r"(r[1]) : "r"(addr));
}
__device__ __forceinline__ void mma16816(float* d, const uint32_t* a, const uint32_t* b){
    asm volatile("mma.sync.aligned.m16n8k16.row.col.f32.bf16.bf16.f32 "
        "{%0,%1,%2,%3}, {%4,%5,%6,%7}, {%8,%9}, {%0,%1,%2,%3};"
        : "+f"(d[0]),"+f"(d[1]),"+f"(d[2]),"+f"(d[3])
        : "r"(a[0]),"r"(a[1]),"r"(a[2]),"r"(a[3]), "r"(b[0]),"r"(b[1]));
}

// ============================================================================
// GroupNorm (validated)
// ============================================================================
__global__ void __launch_bounds__(256)
gn_kernel(const float* __restrict__ x,
          const float* __restrict__ gw,
          const float* __restrict__ gb)
{
    const int GSZ4 = CPG*NHW/4;
    int bg = blockIdx.x;
    int g  = bg & (NG-1);
    const float4* xp = (const float4*)(x + (size_t)bg*CPG*NHW);
    float4*       op = (float4*)(g_xn + (size_t)bg*CPG*NHW);

    float s = 0.f, s2 = 0.f;
    for (int i = threadIdx.x; i < GSZ4; i += 256){
        float4 v = xp[i];
        s  += (v.x+v.y)+(v.z+v.w);
        s2 += (v.x*v.x+v.y*v.y)+(v.z*v.z+v.w*v.w);
    }
    #pragma unroll
    for (int m=16;m;m>>=1){
        s  += __shfl_xor_sync(0xffffffffu, s,  m);
        s2 += __shfl_xor_sync(0xffffffffu, s2, m);
    }
    __shared__ float shA[8], shB[8], shMu, shRs;
    int w = threadIdx.x>>5, l = threadIdx.x&31;
    if (l==0){ shA[w]=s; shB[w]=s2; }
    __syncthreads();
    if (threadIdx.x==0){
        float S=0.f, S2=0.f;
        #pragma unroll
        for (int i=0;i<8;i++){ S+=shA[i]; S2+=shB[i]; }
        const float inv = 1.f/(float)(CPG*NHW);
        float mu  = S*inv;
        float var = S2*inv - mu*mu;
        shMu = mu; shRs = rsqrtf(var + 1e-5f);
    }
    __syncthreads();
    float mu = shMu, rstd = shRs;
    for (int i = threadIdx.x; i < GSZ4; i += 256){
        float4 v = xp[i];
        int cl = i >> 8;
        float a = gw[g*CPG+cl]*rstd;
        float c = gb[g*CPG+cl] - mu*a;
        float4 o;
        o.x=v.x*a+c; o.y=v.y*a+c; o.z=v.z*a+c; o.w=v.w*a+c;
        op[i]=o;
    }
}

// ============================================================================
// Weight converter: fp32 [M][512] -> bf16 hi|lo [M][1024]
// ============================================================================
__global__ void __launch_bounds__(256)
conv_w_kernel(const float* __restrict__ w, __nv_bfloat16* __restrict__ o, int total)
{
    int i = (blockIdx.x*256 + threadIdx.x)*4;
    if (i >= total) return;
    float4 v = *(const float4*)(w + i);
    int m = i >> 9, k = i & 511;
    __nv_bfloat16* row = o + (size_t)m*1024;
    float a[4] = {v.x, v.y, v.z, v.w};
    #pragma unroll
    for (int j=0;j<4;j++){
        __nv_bfloat16 h = __float2bfloat16(a[j]);
        row[k+j]       = h;
        row[512+k+j]   = __float2bfloat16(a[j] - __bfloat162float(h));
    }
}

// ============================================================================
// Activation transpose-converter: fp32 [z][512 k][1024 n] -> bf16 hi|lo
// [z][1024 n][1024 (k|k+512)]      32x32 smem tile transpose
// ============================================================================
__global__ void __launch_bounds__(256)
conv_actT_kernel(const float* __restrict__ in, __nv_bfloat16* __restrict__ out)
{
    __shared__ float t[32][33];
    int n0 = blockIdx.x*32, k0 = blockIdx.y*32, z = blockIdx.z;
    int tx = threadIdx.x, ty = threadIdx.y;
    const float* ip = in + ((size_t)z*NC + k0)*NHW + n0;
    #pragma unroll
    for (int j=0;j<4;j++)
        t[ty*4+j][tx] = ip[(size_t)(ty*4+j)*NHW + tx];
    __syncthreads();
    __nv_bfloat16* op = out + ((size_t)z*NHW + n0)*1024 + k0;
    #pragma unroll
    for (int j=0;j<4;j++){
        int nl = ty*4+j;
        float v = t[tx][nl];
        __nv_bfloat16 h = __float2bfloat16(v);
        op[(size_t)nl*1024 + tx]       = h;
        op[(size_t)nl*1024 + 512 + tx] = __float2bfloat16(v - __bfloat162float(h));
    }
}

// ============================================================================
// HMMA split GEMM:  C[z][m][n] = A[m][:512]*B[z][n][:512]^T + bias[m] (+ res)
// A2 [M][1024] hi|lo row-major; B2t [z][1024 n][1024 k] hi|lo row-major.
// CTA: 128m x 128n; 8 warps = 2(m) x 4(n), each warp 64x32 via m16n8k16.
// K: 8 chunks of 64; per k16-step 3 terms AhBh + AhBl + AlBh.
// smem tiles [128][72] bf16 (144 B stride -> ldmatrix conflict-free).
// ============================================================================
#define TPAD   72
#define TILE_E (128*TPAD)              // bf16 elems per tile
#define TILE_BYTES (TILE_E*2)          // 18432
#define GEMM_SMEM (4*TILE_BYTES)       // 73728

__device__ __forceinline__ void g2s_tile(__nv_bfloat16* dst,
                                         const __nv_bfloat16* src,  // row-major, stride 1024
                                         int koff, int tid)
{
    #pragma unroll
    for (int it=0; it<4; it++){
        int i = tid + it*256;
        int row = i >> 3, seg = i & 7;          // 8 threads x 8 bf16 = 64 cols
        uint4 v = *(const uint4*)(src + (size_t)row*1024 + koff + seg*8);
        *(uint4*)(dst + row*TPAD + seg*8) = v;
    }
}

__global__ void __launch_bounds__(256,2)
mma_gemm_kernel(const __nv_bfloat16* __restrict__ A2,
                const __nv_bfloat16* __restrict__ B2t,
                const float* __restrict__ bias,
                const float* __restrict__ res,
                float* __restrict__ C,
                int M)
{
    extern __shared__ __nv_bfloat16 sm[];
    __nv_bfloat16* sAh = sm;
    __nv_bfloat16* sAl = sm + TILE_E;
    __nv_bfloat16* sBh = sm + 2*TILE_E;
    __nv_bfloat16* sBl = sm + 3*TILE_E;

    const int tid  = threadIdx.x;
    const int warp = tid >> 5, lane = tid & 31;
    const int wm = warp >> 2, wn = warp & 3;    // 2 x 4 warp grid
    const int n0 = blockIdx.x*128, m0 = blockIdx.y*128, z = blockIdx.z;

    const __nv_bfloat16* Ag = A2 + (size_t)m0*1024;
    const __nv_bfloat16* Bg = B2t + ((size_t)z*NHW + n0)*1024;

    // per-thread ldmatrix base offsets (bf16 units)
    const int aOff = (wm*64 + (lane & 15))*TPAD + (lane >> 4)*8;
    const int bOff = (wn*32 + (lane & 7))*TPAD + ((lane >> 3) & 1)*8;
    const uint32_t sAhA = smem_u32(sAh) + aOff*2;
    const uint32_t sAlA = smem_u32(sAl) + aOff*2;
    const uint32_t sBhA = smem_u32(sBh) + bOff*2;
    const uint32_t sBlA = smem_u32(sBl) + bOff*2;

    float acc[4][4][4];
    #pragma unroll
    for (int i=0;i<4;i++)
        #pragma unroll
        for (int j=0;j<4;j++)
            #pragma unroll
            for (int r=0;r<4;r++) acc[i][j][r]=0.f;

    for (int c = 0; c < 8; c++){
        const int kh = c*64, kl = 512 + c*64;
        g2s_tile(sAh, Ag, kh, tid);
        g2s_tile(sAl, Ag, kl, tid);
        g2s_tile(sBh, Bg, kh, tid);
        g2s_tile(sBl, Bg, kl, tid);
        __syncthreads();

        #pragma unroll
        for (int k16 = 0; k16 < 4; k16++){
            const uint32_t kb = k16*32;         // 16 bf16 = 32 bytes
            uint32_t bh[4][2], bl[4][2];
            #pragma unroll
            for (int nt=0; nt<4; nt++){
                ldmx2(bh[nt], sBhA + nt*(8*TPAD*2) + kb);
                ldmx2(bl[nt], sBlA + nt*(8*TPAD*2) + kb);
            }
            #pragma unroll
            for (int mt=0; mt<4; mt++){
                uint32_t ah[4], al[4];
                ldmx4(ah, sAhA + mt*(16*TPAD*2) + kb);
                ldmx4(al, sAlA + mt*(16*TPAD*2) + kb);
                #pragma unroll
                for (int nt=0; nt<4; nt++){
                    mma16816(acc[mt][nt], ah, bh[nt]);
                    mma16816(acc[mt][nt], ah, bl[nt]);
                    mma16816(acc[mt][nt], al, bh[nt]);
                }
            }
        }
        __syncthreads();
    }

    // epilogue: d0,d1 -> (row, 2c..2c+1), d2,d3 -> (row+8, ...)
    const int rBase = m0 + wm*64 + (lane >> 2);
    const int cBase = n0 + wn*32 + (lane & 3)*2;
    #pragma unroll
    for (int mt=0; mt<4; mt++){
        const int r0 = rBase + mt*16;
        const float bi0 = bias[r0], bi1 = bias[r0+8];
        float* cp0 = C + ((size_t)z*M + r0  )*NHW;
        float* cp1 = C + ((size_t)z*M + r0+8)*NHW;
        const float* rp0 = res ? res + ((size_t)z*M + r0  )*NHW : nullptr;
        const float* rp1 = res ? res + ((size_t)z*M + r0+8)*NHW : nullptr;
        #pragma unroll
        for (int nt=0; nt<4; nt++){
            const int cc = cBase + nt*8;
            float2 v0 = make_float2(acc[mt][nt][0]+bi0, acc[mt][nt][1]+bi0);
            float2 v1 = make_float2(acc[mt][nt][2]+bi1, acc[mt][nt][3]+bi1);
            if (rp0){
                float2 a0 = *(const float2*)(rp0 + cc);
                float2 a1 = *(const float2*)(rp1 + cc);
                v0.x+=a0.x; v0.y+=a0.y; v1.x+=a1.x; v1.y+=a1.y;
            }
            *(float2*)(cp0 + cc) = v0;
            *(float2*)(cp1 + cc) = v1;
        }
    }
}

// ============================================================================
// Fused flash attention (fp32, f32x2-packed) — validated
// ============================================================================
__global__ void __launch_bounds__(256,2)
attn_kernel()
{
    extern __shared__ float smf[];
    float* Qs = smf;
    float* Ks = smf + 64*68;
    float* Vs = smf + 2*64*68;
    float* Ps = smf + 3*64*68;

    const int tid = threadIdx.x;
    const int tx = tid & 15, ty = tid >> 4;
    const int qb = ty*4, db = tx*4;
    const int q0 = blockIdx.x*64;
    const int h  = blockIdx.y, b = blockIdx.z;

    const float* qp = g_qkv + ((size_t)b*3*NC + (size_t)h*HD)*NHW;
    const float* kp = qp + (size_t)NC*NHW;
    const float* vp = qp + (size_t)(2*NC)*NHW;
    float*       op = g_att + ((size_t)b*NC + (size_t)h*HD)*NHW;

    #pragma unroll
    for (int it=0; it<4; it++){
        int i = tid + it*256;
        int d = i>>4, f=(i&15)*4;
        *(float4*)&Qs[d*68+f] = *(const float4*)&qp[(size_t)d*NHW + q0 + f];
    }

    float m_run[4], l_run[4];
    u64 acc2[4][2];
    #pragma unroll
    for (int i=0;i<4;i++){
        m_run[i]=-1e30f; l_run[i]=0.f;
        acc2[i][0]=0ull; acc2[i][1]=0ull;
    }
    __syncthreads();

    for (int t=0;t<16;t++){
        const int m0 = t*64;
        #pragma unroll
        for (int it=0; it<4; it++){
            int i = tid + it*256;
            int d = i>>4, f=(i&15)*4;
            *(float4*)&Ks[d*68+f] = *(const float4*)&kp[(size_t)d*NHW + m0 + f];
            float4 vv = *(const float4*)&vp[(size_t)d*NHW + m0 + f];
            Vs[(f+0)*68+d]=vv.x; Vs[(f+1)*68+d]=vv.y;
            Vs[(f+2)*68+d]=vv.z; Vs[(f+3)*68+d]=vv.w;
        }
        __syncthreads();

        u64 s2[4][2];
        #pragma unroll
        for (int i=0;i<4;i++){ s2[i][0]=0ull; s2[i][1]=0ull; }

        #pragma unroll 8
        for (int d=0; d<64; d++){
            float4 qv = *(const float4*)&Qs[d*68+qb];
            const u64* kp2 = (const u64*)&Ks[d*68+db];
            u64 k0=kp2[0], k1=kp2[1];
            u64 a0=bcast2(qv.x), a1=bcast2(qv.y), a2=bcast2(qv.z), a3=bcast2(qv.w);
            ffma2(s2[0][0],a0,k0); ffma2(s2[0][1],a0,k1);
            ffma2(s2[1][0],a1,k0); ffma2(s2[1][1],a1,k1);
            ffma2(s2[2][0],a2,k0); ffma2(s2[2][1],a2,k1);
            ffma2(s2[3][0],a3,k0); ffma2(s2[3][1],a3,k1);
        }

        #pragma unroll
        for (int i=0;i<4;i++){
            float2 pa = unpk(s2[i][0]), pb = unpk(s2[i][1]);
            float s0=pa.x*0.125f, s1=pa.y*0.125f, s2v=pb.x*0.125f, s3=pb.y*0.125f;
            float rmax = fmaxf(fmaxf(s0,s1),fmaxf(s2v,s3));
            #pragma unroll
            for (int mk=1; mk<16; mk<<=1)
                rmax = fmaxf(rmax, __shfl_xor_sync(0xffffffffu, rmax, mk));
            float mn   = fmaxf(m_run[i], rmax);
            float corr = __expf(m_run[i]-mn);
            m_run[i]   = mn;
            float p0=__expf(s0-mn), p1=__expf(s1-mn);
            float p2=__expf(s2v-mn), p3=__expf(s3-mn);
            float rs = (p0+p1)+(p2+p3);
            #pragma unroll
            for (int mk=1; mk<16; mk<<=1)
                rs += __shfl_xor_sync(0xffffffffu, rs, mk);
            l_run[i] = l_run[i]*corr + rs;
            u64 c2 = bcast2(corr);
            fmul2(acc2[i][0], c2);
            fmul2(acc2[i][1], c2);
            *(float4*)&Ps[(qb+i)*68+db] = make_float4(p0,p1,p2,p3);
        }
        __syncthreads();

        #pragma unroll 4
        for (int m=0; m<64; m++){
            const u64* vp2 = (const u64*)&Vs[m*68+db];
            u64 v0=vp2[0], v1=vp2[1];
            u64 b0=bcast2(Ps[(qb+0)*68+m]);
            u64 b1=bcast2(Ps[(qb+1)*68+m]);
            u64 b2=bcast2(Ps[(qb+2)*68+m]);
            u64 b3=bcast2(Ps[(qb+3)*68+m]);
            ffma2(acc2[0][0],b0,v0); ffma2(acc2[0][1],b0,v1);
            ffma2(acc2[1][0],b1,v0); ffma2(acc2[1][1],b1,v1);
            ffma2(acc2[2][0],b2,v0); ffma2(acc2[2][1],b2,v1);
            ffma2(acc2[3][0],b3,v0); ffma2(acc2[3][1],b3,v1);
        }
        __syncthreads();
    }

    #pragma unroll
    for (int i=0;i<4;i++){
        float inv = 1.f/l_run[i];
        float2 pa = unpk(acc2[i][0]), pb = unpk(acc2[i][1]);
        Qs[(db+0)*68 + qb + i] = pa.x*inv;
        Qs[(db+1)*68 + qb + i] = pa.y*inv;
        Qs[(db+2)*68 + qb + i] = pb.x*inv;
        Qs[(db+3)*68 + qb + i] = pb.y*inv;
    }
    __syncthreads();
    #pragma unroll
    for (int it=0; it<4; it++){
        int i = tid + it*256;
        int d = i>>4, f=(i&15)*4;
        *(float4*)&op[(size_t)d*NHW + q0 + f] = *(const float4*)&Qs[d*68+f];
    }
}

// ============================================================================
extern "C" void kernel_launch(void* const* d_in, const int* in_sizes, int n_in,
                              void* d_out, int out_size)
{
    const float* x      = (const float*)d_in[0];
    const float* gn_w   = (const float*)d_in[1];
    const float* gn_b   = (const float*)d_in[2];
    const float* qkv_w  = (const float*)d_in[3];
    const float* qkv_b  = (const float*)d_in[4];
    const float* proj_w = (const float*)d_in[5];
    const float* proj_b = (const float*)d_in[6];
    float* out = (float*)d_out;

    float* xn;  cudaGetSymbolAddress((void**)&xn,  g_xn);
    float* att; cudaGetSymbolAddress((void**)&att, g_att);
    float* qkv; cudaGetSymbolAddress((void**)&qkv, g_qkv);
    __nv_bfloat16 *wA, *wP, *xT, *aT;
    cudaGetSymbolAddress((void**)&wA, g_wA);
    cudaGetSymbolAddress((void**)&wP, g_wP);
    cudaGetSymbolAddress((void**)&xT, g_xT);
    cudaGetSymbolAddress((void**)&aT, g_aT);

    static int attr_set = 0;
    const int ATT_SMEM = 4*64*68*sizeof(float);   // 69632
    if (!attr_set){
        cudaFuncSetAttribute(attn_kernel,
            cudaFuncAttributeMaxDynamicSharedMemorySize, ATT_SMEM);
        cudaFuncSetAttribute(mma_gemm_kernel,
            cudaFuncAttributeMaxDynamicSharedMemorySize, GEMM_SMEM);
        attr_set = 1;
    }

    // 1. GroupNorm -> g_xn (fp32)
    gn_kernel<<<NB*NG, 256>>>(x, gn_w, gn_b);

    // 2. Convert weights + activations to bf16 hi|lo (K-major)
    conv_w_kernel<<<(3*NC*NC)/1024, 256>>>(qkv_w, wA, 3*NC*NC);
    conv_w_kernel<<<(NC*NC)/1024, 256>>>(proj_w, wP, NC*NC);
    conv_actT_kernel<<<dim3(32, 16, NB), dim3(32,8)>>>(xn, xT);

    // 3. QKV GEMM (HMMA): [1536,512]x[512,1024] per z
    mma_gemm_kernel<<<dim3(8, 12, NB), 256, GEMM_SMEM>>>(wA, xT, qkv_b,
                                                         nullptr, qkv, 3*NC);

    // 4. Fused attention -> g_att (fp32)
    attn_kernel<<<dim3(NHW/64, NH, NB), 256, ATT_SMEM>>>();

    // 5. Convert attention output, proj GEMM + residual -> out
    conv_actT_kernel<<<dim3(32, 16, NB), dim3(32,8)>>>(att, aT);
    mma_gemm_kernel<<<dim3(8, 4, NB), 256, GEMM_SMEM>>>(wP, aT, proj_b,
                                                        x, out, NC);
}

// round 9
// speedup vs baseline: 2.6078x; 1.7182x over previous
#include <cuda_runtime.h>
#include <cuda_bf16.h>
#include <cstdint>

#define NB   8
#define NC   512
#define NHW  1024
#define NH   8
#define HD   64
#define NG   32
#define CPG  16

// -------- scratch (static device arrays; no cudaMalloc allowed) --------
__device__ float g_xn [NB*NC*NHW];              // 16 MB  groupnorm output (fp32)
__device__ float g_qkv[NB*3*NC*NHW];            // 48 MB  qkv activations (fp32)
__device__ float g_att[NB*NC*NHW];              // 16 MB  attention output (fp32)
__device__ __nv_bfloat16 g_wA[3*NC*2*NC];       //  3 MB  qkv_w  hi|lo  [1536][1024]
__device__ __nv_bfloat16 g_wP[NC*2*NC];         //  1 MB  proj_w hi|lo  [512][1024]
__device__ __nv_bfloat16 g_xT[NB*NHW*2*NC];     // 16 MB  xn^T hi|lo / QT [bh][1024][128]
__device__ __nv_bfloat16 g_aT[NB*NHW*2*NC];     // 16 MB  KT [bh][1024][128] / att^T hi|lo
__device__ __nv_bfloat16 g_vc[NB*NH*2*HD*NHW];  // 16 MB  V hi|lo planes [bh][128][1024]

// -------- mma.sync helpers (arch-generic) --------
__device__ __forceinline__ uint32_t smem_u32(const void* p){
    uint32_t a;
    asm("{ .reg .u64 t; cvta.to.shared.u64 t, %1; cvt.u32.u64 %0, t; }"
        : "=r"(a) : "l"(p));
    return a;
}
__device__ __forceinline__ void ldmx4(uint32_t* r, uint32_t addr){
    asm volatile("ldmatrix.sync.aligned.m8n8.x4.shared.b16 {%0,%1,%2,%3}, [%4];"
        : "=r"(r[0]),"=r"(r[1]),"=r"(r[2]),"=r"(r[3]) : "r"(addr));
}
__device__ __forceinline__ void ldmx2(uint32_t* r, uint32_t addr){
    asm volatile("ldmatrix.sync.aligned.m8n8.x2.shared.b16 {%0,%1}, [%2];"
        : "=r"(r[0]),"=r"(r[1]) : "r"(addr));
}
__device__ __forceinline__ void mma16816(float* d, const uint32_t* a, const uint32_t* b){
    asm volatile("mma.sync.aligned.m16n8k16.row.col.f32.bf16.bf16.f32 "
        "{%0,%1,%2,%3}, {%4,%5,%6,%7}, {%8,%9}, {%0,%1,%2,%3};"
        : "+f"(d[0]),"+f"(d[1]),"+f"(d[2]),"+f"(d[3])
        : "r"(a[0]),"r"(a[1]),"r"(a[2]),"r"(a[3]), "r"(b[0]),"r"(b[1]));
}

// ============================================================================
// GroupNorm (validated)
// ============================================================================
__global__ void __launch_bounds__(256)
gn_kernel(const float* __restrict__ x,
          const float* __restrict__ gw,
          const float* __restrict__ gb)
{
    const int GSZ4 = CPG*NHW/4;
    int bg = blockIdx.x;
    int g  = bg & (NG-1);
    const float4* xp = (const float4*)(x + (size_t)bg*CPG*NHW);
    float4*       op = (float4*)(g_xn + (size_t)bg*CPG*NHW);

    float s = 0.f, s2 = 0.f;
    for (int i = threadIdx.x; i < GSZ4; i += 256){
        float4 v = xp[i];
        s  += (v.x+v.y)+(v.z+v.w);
        s2 += (v.x*v.x+v.y*v.y)+(v.z*v.z+v.w*v.w);
    }
    #pragma unroll
    for (int m=16;m;m>>=1){
        s  += __shfl_xor_sync(0xffffffffu, s,  m);
        s2 += __shfl_xor_sync(0xffffffffu, s2, m);
    }
    __shared__ float shA[8], shB[8], shMu, shRs;
    int w = threadIdx.x>>5, l = threadIdx.x&31;
    if (l==0){ shA[w]=s; shB[w]=s2; }
    __syncthreads();
    if (threadIdx.x==0){
        float S=0.f, S2=0.f;
        #pragma unroll
        for (int i=0;i<8;i++){ S+=shA[i]; S2+=shB[i]; }
        const float inv = 1.f/(float)(CPG*NHW);
        float mu  = S*inv;
        float var = S2*inv - mu*mu;
        shMu = mu; shRs = rsqrtf(var + 1e-5f);
    }
    __syncthreads();
    float mu = shMu, rstd = shRs;
    for (int i = threadIdx.x; i < GSZ4; i += 256){
        float4 v = xp[i];
        int cl = i >> 8;
        float a = gw[g*CPG+cl]*rstd;
        float c = gb[g*CPG+cl] - mu*a;
        float4 o;
        o.x=v.x*a+c; o.y=v.y*a+c; o.z=v.z*a+c; o.w=v.w*a+c;
        op[i]=o;
    }
}

// ============================================================================
// Weight converter: fp32 [M][512] -> bf16 hi|lo [M][1024]
// ============================================================================
__global__ void __launch_bounds__(256)
conv_w_kernel(const float* __restrict__ w, __nv_bfloat16* __restrict__ o, int total)
{
    int i = (blockIdx.x*256 + threadIdx.x)*4;
    if (i >= total) return;
    float4 v = *(const float4*)(w + i);
    int m = i >> 9, k = i & 511;
    __nv_bfloat16* row = o + (size_t)m*1024;
    float a[4] = {v.x, v.y, v.z, v.w};
    #pragma unroll
    for (int j=0;j<4;j++){
        __nv_bfloat16 h = __float2bfloat16(a[j]);
        row[k+j]       = h;
        row[512+k+j]   = __float2bfloat16(a[j] - __bfloat162float(h));
    }
}

// ============================================================================
// Activation transpose-converter: fp32 [z][512 k][1024 n] -> bf16 hi|lo
// [z][1024 n][1024 (k|k+512)]
// ============================================================================
__global__ void __launch_bounds__(256)
conv_actT_kernel(const float* __restrict__ in, __nv_bfloat16* __restrict__ out)
{
    __shared__ float t[32][33];
    int n0 = blockIdx.x*32, k0 = blockIdx.y*32, z = blockIdx.z;
    int tx = threadIdx.x, ty = threadIdx.y;
    const float* ip = in + ((size_t)z*NC + k0)*NHW + n0;
    #pragma unroll
    for (int j=0;j<4;j++)
        t[ty*4+j][tx] = ip[(size_t)(ty*4+j)*NHW + tx];
    __syncthreads();
    __nv_bfloat16* op = out + ((size_t)z*NHW + n0)*1024 + k0;
    #pragma unroll
    for (int j=0;j<4;j++){
        int nl = ty*4+j;
        float v = t[tx][nl];
        __nv_bfloat16 h = __float2bfloat16(v);
        op[(size_t)nl*1024 + tx]       = h;
        op[(size_t)nl*1024 + 512 + tx] = __float2bfloat16(v - __bfloat162float(h));
    }
}

// ============================================================================
// Q/K transpose-converter: g_qkv [b][c][n] -> out [bh][n 1024][d-hi 64|d-lo 64]
// scale folded in (Q: 1/8, K: 1)
// ============================================================================
__global__ void __launch_bounds__(256)
conv_qkT_kernel(const float* __restrict__ in, __nv_bfloat16* __restrict__ out,
                int coff, float scale)
{
    __shared__ float t[32][33];
    int n0 = blockIdx.x*32, d0 = blockIdx.y*32, bh = blockIdx.z;
    int b = bh >> 3, h = bh & 7;
    int tx = threadIdx.x, ty = threadIdx.y;
    const float* ip = in + ((size_t)b*3*NC + coff + h*HD + d0)*NHW + n0;
    #pragma unroll
    for (int j=0;j<4;j++)
        t[ty*4+j][tx] = ip[(size_t)(ty*4+j)*NHW + tx];
    __syncthreads();
    __nv_bfloat16* op = out + ((size_t)bh*NHW + n0)*128 + d0;
    #pragma unroll
    for (int j=0;j<4;j++){
        int nl = ty*4+j;
        float v = t[tx][nl]*scale;
        __nv_bfloat16 hv = __float2bfloat16(v);
        op[(size_t)nl*128 + tx]      = hv;
        op[(size_t)nl*128 + 64 + tx] = __float2bfloat16(v - __bfloat162float(hv));
    }
}

// ============================================================================
// V converter: g_qkv V part [b][h*64+d][m] -> g_vc [bh][d|d+64][m] hi|lo planes
// ============================================================================
__global__ void __launch_bounds__(256)
conv_v_kernel(const float* __restrict__ in, __nv_bfloat16* __restrict__ out)
{
    int bh = blockIdx.y, b = bh >> 3, h = bh & 7;
    int idx = (blockIdx.x*256 + threadIdx.x)*4;     // 0..65535
    int d = idx >> 10, m = idx & 1023;
    float4 v = *(const float4*)(in + ((size_t)b*3*NC + 2*NC + h*HD + d)*NHW + m);
    __nv_bfloat16* o = out + (size_t)bh*128*1024;
    float a[4] = {v.x, v.y, v.z, v.w};
    __nv_bfloat16 hi[4], lo[4];
    #pragma unroll
    for (int j=0;j<4;j++){
        hi[j] = __float2bfloat16(a[j]);
        lo[j] = __float2bfloat16(a[j] - __bfloat162float(hi[j]));
    }
    *(uint2*)(o + (size_t)d*1024 + m)        = *(uint2*)hi;
    *(uint2*)(o + (size_t)(d+64)*1024 + m)   = *(uint2*)lo;
}

// ============================================================================
// HMMA split GEMM (validated R8)
// ============================================================================
#define TPAD   72
#define TILE_E (128*TPAD)
#define GEMM_SMEM (4*TILE_E*2)

__device__ __forceinline__ void g2s_tile(__nv_bfloat16* dst,
                                         const __nv_bfloat16* src,
                                         int koff, int tid)
{
    #pragma unroll
    for (int it=0; it<4; it++){
        int i = tid + it*256;
        int row = i >> 3, seg = i & 7;
        uint4 v = *(const uint4*)(src + (size_t)row*1024 + koff + seg*8);
        *(uint4*)(dst + row*TPAD + seg*8) = v;
    }
}

__global__ void __launch_bounds__(256,2)
mma_gemm_kernel(const __nv_bfloat16* __restrict__ A2,
                const __nv_bfloat16* __restrict__ B2t,
                const float* __restrict__ bias,
                const float* __restrict__ res,
                float* __restrict__ C,
                int M)
{
    extern __shared__ __nv_bfloat16 sm[];
    __nv_bfloat16* sAh = sm;
    __nv_bfloat16* sAl = sm + TILE_E;
    __nv_bfloat16* sBh = sm + 2*TILE_E;
    __nv_bfloat16* sBl = sm + 3*TILE_E;

    const int tid  = threadIdx.x;
    const int warp = tid >> 5, lane = tid & 31;
    const int wm = warp >> 2, wn = warp & 3;
    const int n0 = blockIdx.x*128, m0 = blockIdx.y*128, z = blockIdx.z;

    const __nv_bfloat16* Ag = A2 + (size_t)m0*1024;
    const __nv_bfloat16* Bg = B2t + ((size_t)z*NHW + n0)*1024;

    const int aOff = (wm*64 + (lane & 15))*TPAD + (lane >> 4)*8;
    const int bOff = (wn*32 + (lane & 7))*TPAD + ((lane >> 3) & 1)*8;
    const uint32_t sAhA = smem_u32(sAh) + aOff*2;
    const uint32_t sAlA = smem_u32(sAl) + aOff*2;
    const uint32_t sBhA = smem_u32(sBh) + bOff*2;
    const uint32_t sBlA = smem_u32(sBl) + bOff*2;

    float acc[4][4][4];
    #pragma unroll
    for (int i=0;i<4;i++)
        #pragma unroll
        for (int j=0;j<4;j++)
            #pragma unroll
            for (int r=0;r<4;r++) acc[i][j][r]=0.f;

    for (int c = 0; c < 8; c++){
        const int kh = c*64, kl = 512 + c*64;
        g2s_tile(sAh, Ag, kh, tid);
        g2s_tile(sAl, Ag, kl, tid);
        g2s_tile(sBh, Bg, kh, tid);
        g2s_tile(sBl, Bg, kl, tid);
        __syncthreads();

        #pragma unroll
        for (int k16 = 0; k16 < 4; k16++){
            const uint32_t kb = k16*32;
            uint32_t bh[4][2], bl[4][2];
            #pragma unroll
            for (int nt=0; nt<4; nt++){
                ldmx2(bh[nt], sBhA + nt*(8*TPAD*2) + kb);
                ldmx2(bl[nt], sBlA + nt*(8*TPAD*2) + kb);
            }
            #pragma unroll
            for (int mt=0; mt<4; mt++){
                uint32_t ah[4], al[4];
                ldmx4(ah, sAhA + mt*(16*TPAD*2) + kb);
                ldmx4(al, sAlA + mt*(16*TPAD*2) + kb);
                #pragma unroll
                for (int nt=0; nt<4; nt++){
                    mma16816(acc[mt][nt], ah, bh[nt]);
                    mma16816(acc[mt][nt], ah, bl[nt]);
                    mma16816(acc[mt][nt], al, bh[nt]);
                }
            }
        }
        __syncthreads();
    }

    const int rBase = m0 + wm*64 + (lane >> 2);
    const int cBase = n0 + wn*32 + (lane & 3)*2;
    #pragma unroll
    for (int mt=0; mt<4; mt++){
        const int r0 = rBase + mt*16;
        const float bi0 = bias[r0], bi1 = bias[r0+8];
        float* cp0 = C + ((size_t)z*M + r0  )*NHW;
        float* cp1 = C + ((size_t)z*M + r0+8)*NHW;
        const float* rp0 = res ? res + ((size_t)z*M + r0  )*NHW : nullptr;
        const float* rp1 = res ? res + ((size_t)z*M + r0+8)*NHW : nullptr;
        #pragma unroll
        for (int nt=0; nt<4; nt++){
            const int cc = cBase + nt*8;
            float2 v0 = make_float2(acc[mt][nt][0]+bi0, acc[mt][nt][1]+bi0);
            float2 v1 = make_float2(acc[mt][nt][2]+bi1, acc[mt][nt][3]+bi1);
            if (rp0){
                float2 a0 = *(const float2*)(rp0 + cc);
                float2 a1 = *(const float2*)(rp1 + cc);
                v0.x+=a0.x; v0.y+=a0.y; v1.x+=a1.x; v1.y+=a1.y;
            }
            *(float2*)(cp0 + cc) = v0;
            *(float2*)(cp1 + cc) = v1;
        }
    }
}

// ============================================================================
// HMMA flash attention. Block per (q-tile 128, bh). 8 warps; warp owns 16 q
// rows x full 128 m. smem tiles stride 136; Q/K [row][hi64|lo64];
// V [hi d64 rows | lo d64 rows][m]; Ph/Pl [q][m].
// 3-term hi/lo split on both GEMMs; online softmax warp-local (quad shfl).
// ============================================================================
#define AST 136
#define ATE (128*AST)                   // 17408 elems per tile
#define ATT_SMEM (5*ATE*2)              // 174080 B

__global__ void __launch_bounds__(256)
attn_mma_kernel(const __nv_bfloat16* __restrict__ QT,
                const __nv_bfloat16* __restrict__ KT,
                const __nv_bfloat16* __restrict__ Vc)
{
    extern __shared__ __nv_bfloat16 sm[];
    __nv_bfloat16* sQ  = sm;
    __nv_bfloat16* sK  = sm + ATE;
    __nv_bfloat16* sV  = sm + 2*ATE;
    __nv_bfloat16* sPh = sm + 3*ATE;
    __nv_bfloat16* sPl = sm + 4*ATE;

    const int tid = threadIdx.x, warp = tid >> 5, lane = tid & 31;
    const int q0 = blockIdx.x*128, bh = blockIdx.y;
    const int qrow = warp*16;

    const __nv_bfloat16* Qg = QT + ((size_t)bh*NHW + q0)*128;
    const __nv_bfloat16* Kg = KT + (size_t)bh*NHW*128;
    const __nv_bfloat16* Vg = Vc + (size_t)bh*128*1024;

    // load Q tile once: 128 rows x 128 bf16
    #pragma unroll
    for (int it=0; it<8; it++){
        int i = tid + it*256;
        int row = i >> 4, seg = i & 15;
        *(uint4*)(sQ + row*AST + seg*8) = *(const uint4*)(Qg + (size_t)row*128 + seg*8);
    }

    const uint32_t aQ  = smem_u32(sQ)  + ((qrow + (lane&15))*AST + (lane>>4)*8)*2;
    const uint32_t aPh = smem_u32(sPh) + ((qrow + (lane&15))*AST + (lane>>4)*8)*2;
    const uint32_t aPl = smem_u32(sPl) + ((qrow + (lane&15))*AST + (lane>>4)*8)*2;
    const uint32_t bK  = smem_u32(sK)  + (((lane&7))*AST + ((lane>>3)&1)*8)*2;
    const uint32_t bV  = smem_u32(sV)  + (((lane&7))*AST + ((lane>>3)&1)*8)*2;

    float m0r = -1e30f, m1r = -1e30f, l0r = 0.f, l1r = 0.f;
    float o[8][4];
    #pragma unroll
    for (int i=0;i<8;i++){ o[i][0]=0.f; o[i][1]=0.f; o[i][2]=0.f; o[i][3]=0.f; }

    const int r0 = qrow + (lane>>2);
    const int pcol = (lane&3)*2;

    for (int t = 0; t < 8; t++){
        const int mm0 = t*128;
        __syncthreads();
        #pragma unroll
        for (int it=0; it<8; it++){
            int i = tid + it*256;
            int row = i >> 4, seg = i & 15;
            *(uint4*)(sK + row*AST + seg*8) =
                *(const uint4*)(Kg + (size_t)(mm0+row)*128 + seg*8);
            *(uint4*)(sV + row*AST + seg*8) =
                *(const uint4*)(Vg + (size_t)row*1024 + mm0 + seg*8);
        }
        __syncthreads();

        // ---- S = Q K^T (3-term), s[16 nt][4] ----
        float s[16][4];
        #pragma unroll
        for (int i=0;i<16;i++){ s[i][0]=0.f; s[i][1]=0.f; s[i][2]=0.f; s[i][3]=0.f; }

        #pragma unroll
        for (int k16=0; k16<4; k16++){
            const uint32_t kb = k16*32;
            uint32_t qh[4], ql[4];
            ldmx4(qh, aQ + kb);
            ldmx4(ql, aQ + 128 + kb);
            #pragma unroll
            for (int nt=0; nt<16; nt++){
                uint32_t kh[2], kl[2];
                ldmx2(kh, bK + nt*(8*AST*2) + kb);
                ldmx2(kl, bK + nt*(8*AST*2) + 128 + kb);
                mma16816(s[nt], qh, kh);
                mma16816(s[nt], qh, kl);
                mma16816(s[nt], ql, kh);
            }
        }

        // ---- online softmax, rows r0 and r0+8 (warp-local) ----
        {
            float mx = -1e30f;
            #pragma unroll
            for (int nt=0; nt<16; nt++) mx = fmaxf(mx, fmaxf(s[nt][0], s[nt][1]));
            mx = fmaxf(mx, __shfl_xor_sync(0xffffffffu, mx, 1));
            mx = fmaxf(mx, __shfl_xor_sync(0xffffffffu, mx, 2));
            float mn = fmaxf(m0r, mx);
            float corr = __expf(m0r - mn);
            m0r = mn;
            float sum = 0.f;
            #pragma unroll
            for (int nt=0; nt<16; nt++){
                float p0 = __expf(s[nt][0]-mn), p1 = __expf(s[nt][1]-mn);
                sum += p0+p1;
                __nv_bfloat162 hv = __floats2bfloat162_rn(p0, p1);
                __nv_bfloat162 lv = __floats2bfloat162_rn(
                    p0 - __bfloat162float(hv.x), p1 - __bfloat162float(hv.y));
                *(__nv_bfloat162*)&sPh[r0*AST + nt*8 + pcol] = hv;
                *(__nv_bfloat162*)&sPl[r0*AST + nt*8 + pcol] = lv;
            }
            sum += __shfl_xor_sync(0xffffffffu, sum, 1);
            sum += __shfl_xor_sync(0xffffffffu, sum, 2);
            l0r = l0r*corr + sum;
            #pragma unroll
            for (int i=0;i<8;i++){ o[i][0]*=corr; o[i][1]*=corr; }
        }
        {
            float mx = -1e30f;
            #pragma unroll
            for (int nt=0; nt<16; nt++) mx = fmaxf(mx, fmaxf(s[nt][2], s[nt][3]));
            mx = fmaxf(mx, __shfl_xor_sync(0xffffffffu, mx, 1));
            mx = fmaxf(mx, __shfl_xor_sync(0xffffffffu, mx, 2));
            float mn = fmaxf(m1r, mx);
            float corr = __expf(m1r - mn);
            m1r = mn;
            float sum = 0.f;
            #pragma unroll
            for (int nt=0; nt<16; nt++){
                float p0 = __expf(s[nt][2]-mn), p1 = __expf(s[nt][3]-mn);
                sum += p0+p1;
                __nv_bfloat162 hv = __floats2bfloat162_rn(p0, p1);
                __nv_bfloat162 lv = __floats2bfloat162_rn(
                    p0 - __bfloat162float(hv.x), p1 - __bfloat162float(hv.y));
                *(__nv_bfloat162*)&sPh[(r0+8)*AST + nt*8 + pcol] = hv;
                *(__nv_bfloat162*)&sPl[(r0+8)*AST + nt*8 + pcol] = lv;
            }
            sum += __shfl_xor_sync(0xffffffffu, sum, 1);
            sum += __shfl_xor_sync(0xffffffffu, sum, 2);
            l1r = l1r*corr + sum;
            #pragma unroll
            for (int i=0;i<8;i++){ o[i][2]*=corr; o[i][3]*=corr; }
        }
        __syncwarp();

        // ---- O += P V^T (3-term); V lo plane = rows 64..127 ----
        #pragma unroll
        for (int k16=0; k16<8; k16++){
            const uint32_t kb = k16*32;
            uint32_t ph[4], pl[4];
            ldmx4(ph, aPh + kb);
            ldmx4(pl, aPl + kb);
            #pragma unroll
            for (int nt=0; nt<8; nt++){
                uint32_t vh[2], vl[2];
                ldmx2(vh, bV + nt*(8*AST*2) + kb);
                ldmx2(vl, bV + nt*(8*AST*2) + 64*AST*2 + kb);
                mma16816(o[nt], ph, vh);
                mma16816(o[nt], ph, vl);
                mma16816(o[nt], pl, vh);
            }
        }
    }

    // ---- normalize, stage O[q][d] in smem (reuse sPh as float buffer), write ----
    float inv0 = 1.f/l0r, inv1 = 1.f/l1r;
    float* Os = (float*)sPh;        // [128 q][68 f32] = 34816 B, row-aligned with P rows
    #pragma unroll
    for (int nt=0; nt<8; nt++){
        *(float2*)&Os[r0*68 + nt*8 + pcol] =
            make_float2(o[nt][0]*inv0, o[nt][1]*inv0);
        *(float2*)&Os[(r0+8)*68 + nt*8 + pcol] =
            make_float2(o[nt][2]*inv1, o[nt][3]*inv1);
    }
    __syncthreads();

    float* op = g_att + ((size_t)(bh>>3)*NC + (size_t)(bh&7)*HD)*NHW;
    const int d = tid >> 2, l4 = tid & 3;
    #pragma unroll
    for (int j=0; j<8; j++){
        int q = l4*4 + j*16;
        float4 v;
        v.x = Os[(q+0)*68 + d];
        v.y = Os[(q+1)*68 + d];
        v.z = Os[(q+2)*68 + d];
        v.w = Os[(q+3)*68 + d];
        *(float4*)(op + (size_t)d*NHW + q0 + q) = v;
    }
}

// ============================================================================
extern "C" void kernel_launch(void* const* d_in, const int* in_sizes, int n_in,
                              void* d_out, int out_size)
{
    const float* x      = (const float*)d_in[0];
    const float* gn_w   = (const float*)d_in[1];
    const float* gn_b   = (const float*)d_in[2];
    const float* qkv_w  = (const float*)d_in[3];
    const float* qkv_b  = (const float*)d_in[4];
    const float* proj_w = (const float*)d_in[5];
    const float* proj_b = (const float*)d_in[6];
    float* out = (float*)d_out;

    float* xn;  cudaGetSymbolAddress((void**)&xn,  g_xn);
    float* att; cudaGetSymbolAddress((void**)&att, g_att);
    float* qkv; cudaGetSymbolAddress((void**)&qkv, g_qkv);
    __nv_bfloat16 *wA, *wP, *xT, *aT, *vc;
    cudaGetSymbolAddress((void**)&wA, g_wA);
    cudaGetSymbolAddress((void**)&wP, g_wP);
    cudaGetSymbolAddress((void**)&xT, g_xT);
    cudaGetSymbolAddress((void**)&aT, g_aT);
    cudaGetSymbolAddress((void**)&vc, g_vc);

    static int attr_set = 0;
    if (!attr_set){
        cudaFuncSetAttribute(attn_mma_kernel,
            cudaFuncAttributeMaxDynamicSharedMemorySize, ATT_SMEM);
        cudaFuncSetAttribute(mma_gemm_kernel,
            cudaFuncAttributeMaxDynamicSharedMemorySize, GEMM_SMEM);
        attr_set = 1;
    }

    // 1. GroupNorm -> g_xn
    gn_kernel<<<NB*NG, 256>>>(x, gn_w, gn_b);

    // 2. Convert weights + activations (hi|lo bf16, K-major)
    conv_w_kernel<<<(3*NC*NC)/1024, 256>>>(qkv_w, wA, 3*NC*NC);
    conv_w_kernel<<<(NC*NC)/1024, 256>>>(proj_w, wP, NC*NC);
    conv_actT_kernel<<<dim3(32, 16, NB), dim3(32,8)>>>(xn, xT);

    // 3. QKV GEMM (HMMA) -> g_qkv
    mma_gemm_kernel<<<dim3(8, 12, NB), 256, GEMM_SMEM>>>(wA, xT, qkv_b,
                                                         nullptr, qkv, 3*NC);

    // 4. Convert Q (scaled 1/8, ->xT), K (->aT), V (->vc)
    conv_qkT_kernel<<<dim3(32, 2, NB*NH), dim3(32,8)>>>(qkv, xT, 0,    0.125f);
    conv_qkT_kernel<<<dim3(32, 2, NB*NH), dim3(32,8)>>>(qkv, aT, NC,   1.0f);
    conv_v_kernel<<<dim3(64, NB*NH), 256>>>(qkv, vc);

    // 5. HMMA flash attention -> g_att
    attn_mma_kernel<<<dim3(8, NB*NH), 256, ATT_SMEM>>>(xT, aT, vc);

    // 6. Convert attention output (->aT, overwrites KT), proj GEMM + residual
    conv_actT_kernel<<<dim3(32, 16, NB), dim3(32,8)>>>(att, aT);
    mma_gemm_kernel<<<dim3(8, 4, NB), 256, GEMM_SMEM>>>(wP, aT, proj_b,
                                                        x, out, NC);
}